// round 7
// baseline (speedup 1.0000x reference)
#include <cuda_runtime.h>
#include <math.h>

#define B   64
#define S   96
#define E   300
#define D   512
#define H   256
#define SEL 128
#define G5  1280   // 5*H
#define MLPD 1024
#define NC  3

#define CL  4      // cluster size
#define TPB 256    // threads per scan CTA

typedef unsigned long long ull;

// ---- static device scratch (no allocs allowed) ----
__device__ __align__(16) float g_states[B][S][D];     // 12.6 MB, L2-resident
__device__ float g_logits0[B][S - 1];
__device__ float g_hroot[B][H];
__device__ float g_x1[B][MLPD];
__device__ float g_x2[B][MLPD];
__device__ float g_newlg[B][2];

__device__ __forceinline__ float sigf(float x) { return 1.0f / (1.0f + expf(-x)); }

__device__ __forceinline__ ull fma2(ull a, ull b, ull c) {
    ull d;
    asm("fma.rn.f32x2 %0, %1, %2, %3;" : "=l"(d) : "l"(a), "l"(b), "l"(c));
    return d;
}
__device__ __forceinline__ ull pack2(float x, float y) {
    ull d;
    asm("mov.b64 %0, {%1, %2};" : "=l"(d) : "f"(x), "f"(y));
    return d;
}
__device__ __forceinline__ float lo32(ull v) { return __uint_as_float((unsigned)(v & 0xffffffffull)); }
__device__ __forceinline__ float hi32(ull v) { return __uint_as_float((unsigned)(v >> 32)); }

// full cluster barrier with cluster-scope fences on both sides
// (fence scope >= cluster => L1D invalidate, so post-sync global reads are fresh)
__device__ __forceinline__ void cluster_sync_full() {
    asm volatile("fence.acq_rel.cluster;" ::: "memory");
    asm volatile("barrier.cluster.arrive.aligned;" ::: "memory");
    asm volatile("barrier.cluster.wait.aligned;" ::: "memory");
    asm volatile("fence.acq_rel.cluster;" ::: "memory");
}

// Pair-logit partial used by initsel (initial 95 logits per batch).
__device__ __forceinline__ float pair_logit_partial(
    const float* __restrict__ hL, const float* __restrict__ hR,
    const float* __restrict__ Ws1, const float* __restrict__ bs1,
    const float* __restrict__ Ws2, int j)
{
    float a[8];
#pragma unroll
    for (int m = 0; m < 8; m++) a[m] = 0.0f;
    const float* wp = Ws1 + j;
    for (int k = 0; k < 64; k++) {
#pragma unroll
        for (int m = 0; m < 4; m++)
            a[m] = __fmaf_rn(hL[m * 64 + k], wp[(m * 64 + k) * SEL], a[m]);
#pragma unroll
        for (int m = 0; m < 4; m++)
            a[4 + m] = __fmaf_rn(hR[m * 64 + k], wp[(256 + m * 64 + k) * SEL], a[4 + m]);
    }
    float s = a[0] + a[1] + a[2] + a[3] + a[4] + a[5] + a[6] + a[7] + bs1[j];
    return tanhf(s) * Ws2[j];
}

// ======================================================================
// Kernel 1: encode
// ======================================================================
__global__ void encode_kernel(const int* __restrict__ sent,
                              const float* __restrict__ emb,
                              const float* __restrict__ Wenc,
                              const float* __restrict__ benc) {
    __shared__ float xs[8][E];
    __shared__ int tok[8];
    int row0 = blockIdx.x * 8;
    int tid = threadIdx.x;
    if (tid < 8) tok[tid] = sent[row0 + tid];
    __syncthreads();
    for (int i = tid; i < 8 * E; i += 128) {
        int r = i / E, k = i - r * E;
        xs[r][k] = emb[(long)tok[r] * E + k];
    }
    __syncthreads();
    int c = tid * 4;
    float4 acc[8];
#pragma unroll
    for (int r = 0; r < 8; r++) acc[r] = make_float4(0.f, 0.f, 0.f, 0.f);
    for (int k = 0; k < E; k++) {
        float4 w = *(const float4*)&Wenc[k * D + c];
#pragma unroll
        for (int r = 0; r < 8; r++) {
            float xv = xs[r][k];
            acc[r].x = __fmaf_rn(xv, w.x, acc[r].x);
            acc[r].y = __fmaf_rn(xv, w.y, acc[r].y);
            acc[r].z = __fmaf_rn(xv, w.z, acc[r].z);
            acc[r].w = __fmaf_rn(xv, w.w, acc[r].w);
        }
    }
    float4 bv = *(const float4*)&benc[c];
#pragma unroll
    for (int r = 0; r < 8; r++) {
        acc[r].x += bv.x; acc[r].y += bv.y; acc[r].z += bv.z; acc[r].w += bv.w;
        int gr = row0 + r;
        int b = gr / S, s = gr - b * S;
        *(float4*)&g_states[b][s][c] = acc[r];
    }
}

// ======================================================================
// Kernel 2: initial pair logits (95 per batch)
// ======================================================================
__global__ void initsel_kernel(const float* __restrict__ Ws1,
                               const float* __restrict__ bs1,
                               const float* __restrict__ Ws2,
                               const float* __restrict__ bs2) {
    __shared__ float hs[17][H];
    __shared__ float red[4];
    int b = blockIdx.y;
    int p0 = blockIdx.x * 16;
    int tid = threadIdx.x;
    int nrows = min(17, S - p0);
    for (int i = tid; i < nrows * H; i += 128) {
        int r = i >> 8, k = i & (H - 1);
        hs[r][k] = g_states[b][p0 + r][H + k];
    }
    __syncthreads();
    int npairs = min(16, (S - 1) - p0);
    for (int p = 0; p < npairs; p++) {
        float y = pair_logit_partial(hs[p], hs[p + 1], Ws1, bs1, Ws2, tid);
        for (int o = 16; o; o >>= 1)
            y += __shfl_xor_sync(0xffffffffu, y, o);
        if ((tid & 31) == 0) red[tid >> 5] = y;
        __syncthreads();
        if (tid == 0)
            g_logits0[b][p0 + p] = red[0] + red[1] + red[2] + red[3] + bs2[0];
        __syncthreads();
    }
}

// ======================================================================
// Kernel 3: the scan. 64 CTAs as 16 clusters of 4.
// Cluster owns 4 batches; CTA r owns gate columns for h in [64r, 64r+64).
// ======================================================================
__global__ void __cluster_dims__(CL, 1, 1) __launch_bounds__(TPB, 1)
scan_kernel(const float* __restrict__ Wc,  const float* __restrict__ bc,
            const float* __restrict__ Ws1, const float* __restrict__ bs1,
            const float* __restrict__ Ws2, const float* __restrict__ bs2) {
    __shared__ __align__(16) ull   xs2[4][D];      // (x,x) packed per batch
    __shared__ __align__(16) ull   xpel[D];        // (pairA, pairB) packed, own batch
    __shared__ __align__(16) ull   p5[2][SEL];     // phase-5 k-half partials
    __shared__ __align__(16) float sgate[4][5][64];
    __shared__ float lg[4][S];
    __shared__ int   pm[4][S];
    __shared__ float amaxv[4][2];
    __shared__ int   amaxi_[4][2];
    __shared__ int   selidx[4], sLs[4], sRs[4];
    __shared__ float red5[2][4];

    int tid = threadIdx.x;
    int r   = blockIdx.x & (CL - 1);        // rank in cluster
    int gb0 = blockIdx.x & ~(CL - 1);       // first batch of cluster (4 per cluster)

    // replicated init of lg / pm
    for (int i = tid; i < 4 * (S - 1); i += TPB) {
        int b = i / (S - 1), j = i - b * (S - 1);
        lg[b][j] = g_logits0[gb0 + b][j];
    }
    for (int i = tid; i < 4 * S; i += TPB) {
        int b = i / S, j = i - b * S;
        pm[b][j] = j;
    }
    __syncthreads();

    for (int t = 0; t < S - 1; t++) {
        int n = S - t;
        int np = n - 1;

        // ---- argmax (replicated; 64 threads per batch) ----
        {
            int b = tid >> 6, lt = tid & 63;
            float best = -1e30f; int bi = 0;
            for (int j = lt; j < np; j += 64) {
                float v = lg[b][j];
                if (v > best) { best = v; bi = j; }
            }
            for (int o = 16; o; o >>= 1) {
                float ov = __shfl_xor_sync(0xffffffffu, best, o);
                int   oi = __shfl_xor_sync(0xffffffffu, bi, o);
                if (ov > best || (ov == best && oi < bi)) { best = ov; bi = oi; }
            }
            if ((lt & 31) == 0) { amaxv[b][lt >> 5] = best; amaxi_[b][lt >> 5] = bi; }
        }
        __syncthreads();
        if (tid < 4) {
            int b = tid;
            float v0 = amaxv[b][0], v1 = amaxv[b][1];
            int   i0 = amaxi_[b][0], i1 = amaxi_[b][1];
            int bi = (v1 > v0 || (v1 == v0 && i1 < i0)) ? i1 : i0;
            selidx[b] = bi;
            sLs[b] = pm[b][bi];
            sRs[b] = pm[b][bi + 1];
        }
        __syncthreads();

        // ---- xs staging: packed (x,x) for all 4 batches ----
        for (int i = tid; i < 4 * D; i += TPB) {
            int b = i >> 9, k = i & (D - 1);
            int slot = (k < H) ? sLs[b] : sRs[b];
            int col  = (k < H) ? (H + k) : k;
            float xv = g_states[gb0 + b][slot][col];
            xs2[b][k] = pack2(xv, xv);
        }
        // all CTAs must finish READING old states before any CTA overwrites
        cluster_sync_full();                                     // SYNC 0

        // ---- compose: 160 threads, 2 cols x 4 batches each ----
        if (tid < 160) {
            int g = tid >> 5, u2 = (tid & 31) << 1;
            int c = g * 256 + r * 64 + u2;
            ull bias = pack2(bc[c], bc[c + 1]);
            ull a0 = bias, a1 = bias, a2 = bias, a3 = bias;
            const float* wp = Wc + c;
#pragma unroll 4
            for (int k = 0; k < D; k += 2) {
                ull w0 = *(const ull*)(wp + (size_t)k * G5);
                ull w1 = *(const ull*)(wp + (size_t)(k + 1) * G5);
                ulonglong2 x0 = *(const ulonglong2*)&xs2[0][k];
                ulonglong2 x1 = *(const ulonglong2*)&xs2[1][k];
                ulonglong2 x2 = *(const ulonglong2*)&xs2[2][k];
                ulonglong2 x3 = *(const ulonglong2*)&xs2[3][k];
                a0 = fma2(w0, x0.x, a0); a0 = fma2(w1, x0.y, a0);
                a1 = fma2(w0, x1.x, a1); a1 = fma2(w1, x1.y, a1);
                a2 = fma2(w0, x2.x, a2); a2 = fma2(w1, x2.y, a2);
                a3 = fma2(w0, x3.x, a3); a3 = fma2(w1, x3.y, a3);
            }
            *(ull*)&sgate[0][g][u2] = a0;
            *(ull*)&sgate[1][g][u2] = a1;
            *(ull*)&sgate[2][g][u2] = a2;
            *(ull*)&sgate[3][g][u2] = a3;
        }
        __syncthreads();

        // ---- gates for h in [64r, 64r+64), all 4 batches ----
        {
            int b = tid >> 6, u = tid & 63;
            int h = r * 64 + u;
            int gb = gb0 + b;
            float gi = sgate[b][0][u];
            float fl = sgate[b][1][u];
            float fr = sgate[b][2][u];
            float go = sgate[b][3][u];
            float gc = sgate[b][4][u];
            float cl = g_states[gb][sLs[b]][h];
            float cr = g_states[gb][sRs[b]][h];
            float cc = sigf(fl) * cl + sigf(fr) * cr + sigf(gi) * tanhf(gc);
            float hp = sigf(go) * tanhf(cc);
            g_states[gb][sLs[b]][h]     = cc;
            g_states[gb][sLs[b]][H + h] = hp;
        }
        // state updates must be cluster-visible before phase 4/5 reads
        cluster_sync_full();                                     // SYNC 1

        // ---- shift pm / lg locally (replicated) ----
        {
            int i0 = tid, i1 = tid + TPB;
            int b0 = i0 / 96, j0 = i0 - b0 * 96;
            float pv0 = 0.f, lv0 = 0.f; int wp0 = 0, wl0 = 0;
            {
                int idx = selidx[b0];
                if (j0 >= idx + 1 && j0 <= n - 2) { pv0 = __int_as_float(pm[b0][j0 + 1]); wp0 = 1; }
                if (j0 >= idx + 1 && j0 <= n - 3) { lv0 = lg[b0][j0 + 1]; wl0 = 1; }
            }
            int b1 = 0, j1 = 0; float pv1 = 0.f, lv1 = 0.f; int wp1 = 0, wl1 = 0;
            if (i1 < 384) {
                b1 = i1 / 96; j1 = i1 - b1 * 96;
                int idx = selidx[b1];
                if (j1 >= idx + 1 && j1 <= n - 2) { pv1 = __int_as_float(pm[b1][j1 + 1]); wp1 = 1; }
                if (j1 >= idx + 1 && j1 <= n - 3) { lv1 = lg[b1][j1 + 1]; wl1 = 1; }
            }
            __syncthreads();
            if (wp0) pm[b0][j0] = __float_as_int(pv0);
            if (wl0) lg[b0][j0] = lv0;
            if (wp1) pm[b1][j1] = __float_as_int(pv1);
            if (wl1) lg[b1][j1] = lv1;
        }
        __syncthreads();

        // ---- xsel staging: own batch (gb0+r), both new pairs packed ----
        {
            int idx = selidx[r];
            int q0 = idx - 1, q1 = idx;
            bool vA = (q0 >= 0) && (q0 <= n - 3);
            bool vB = (q1 <= n - 3);
            for (int k = tid; k < D; k += TPB) {
                int col = (k < H) ? (H + k) : k;
                float xA = 0.f, xB = 0.f;
                if (vA) xA = g_states[gb0 + r][(k < H) ? pm[r][q0] : pm[r][q0 + 1]][col];
                if (vB) xB = g_states[gb0 + r][(k < H) ? pm[r][q1] : pm[r][q1 + 1]][col];
                xpel[k] = pack2(xA, xB);
            }
        }
        __syncthreads();

        // ---- phase 5: own batch's 2 pair logits (k split over 2 halves) ----
        {
            int j = tid & 127, kh = tid >> 7;
            const float* wp = Ws1 + j;
            ull acc0 = 0ull, acc1 = 0ull;
            int k0 = kh << 8;
#pragma unroll 8
            for (int k = k0; k < k0 + 256; k += 2) {
                float w0 = wp[(size_t)k * SEL];
                float w1 = wp[(size_t)(k + 1) * SEL];
                ulonglong2 xv = *(const ulonglong2*)&xpel[k];
                acc0 = fma2(pack2(w0, w0), xv.x, acc0);
                acc1 = fma2(pack2(w1, w1), xv.y, acc1);
            }
            p5[kh][j] = pack2(lo32(acc0) + lo32(acc1), hi32(acc0) + hi32(acc1));
        }
        __syncthreads();
        if (tid < 128) {
            int j = tid;
            ull u0 = p5[0][j], u1 = p5[1][j];
            float sA = lo32(u0) + lo32(u1) + bs1[j];
            float sB = hi32(u0) + hi32(u1) + bs1[j];
            float yA = tanhf(sA) * Ws2[j];
            float yB = tanhf(sB) * Ws2[j];
            for (int o = 16; o; o >>= 1) {
                yA += __shfl_xor_sync(0xffffffffu, yA, o);
                yB += __shfl_xor_sync(0xffffffffu, yB, o);
            }
            if ((j & 31) == 0) { red5[0][j >> 5] = yA; red5[1][j >> 5] = yB; }
        }
        __syncthreads();
        if (tid < 2) {
            g_newlg[gb0 + r][tid] =
                red5[tid][0] + red5[tid][1] + red5[tid][2] + red5[tid][3] + bs2[0];
        }
        // new logits must be cluster-visible
        cluster_sync_full();                                     // SYNC 2

        // ---- update local lg replicas from all 4 batches ----
        if (tid < 8) {
            int b = tid >> 1, s = tid & 1;
            int q = selidx[b] - 1 + s;
            if (q >= 0 && q <= n - 3)
                lg[b][q] = g_newlg[gb0 + b][s];
        }
        __syncthreads();
    }

    // ---- root hidden: own h-range, all 4 batches ----
    {
        int b = tid >> 6, u = tid & 63;
        int h = r * 64 + u;
        g_hroot[gb0 + b][h] = g_states[gb0 + b][pm[b][0]][H + h];
    }
}

// ======================================================================
// MLP as 3 column-parallel kernels
// ======================================================================
__global__ void mlp_l1(const float* __restrict__ Wm1, const float* __restrict__ bm1) {
    __shared__ float hsh[H];
    int b = blockIdx.y;
    int c = blockIdx.x * 256 + threadIdx.x;
    if (threadIdx.x < H) hsh[threadIdx.x] = g_hroot[b][threadIdx.x];
    __syncthreads();
    float acc = bm1[c];
    const float* wp = Wm1 + c;
#pragma unroll 8
    for (int k = 0; k < H; k++)
        acc = __fmaf_rn(hsh[k], wp[k * MLPD], acc);
    g_x1[b][c] = fmaxf(acc, 0.0f);
}

__global__ void mlp_l2(const float* __restrict__ Wm2, const float* __restrict__ bm2) {
    __shared__ float x1s[MLPD];
    int b = blockIdx.y;
    int c = blockIdx.x * 256 + threadIdx.x;
    for (int i = threadIdx.x; i < MLPD; i += 256) x1s[i] = g_x1[b][i];
    __syncthreads();
    float acc = bm2[c];
    const float* wp = Wm2 + c;
#pragma unroll 8
    for (int k = 0; k < MLPD; k++)
        acc = __fmaf_rn(x1s[k], wp[k * MLPD], acc);
    g_x2[b][c] = fmaxf(acc, 0.0f);
}

__global__ void mlp_l3(const float* __restrict__ Wout, const float* __restrict__ bout,
                       float* __restrict__ out) {
    __shared__ float red[4][NC];
    int b = blockIdx.x;
    int tid = threadIdx.x;
    float p0 = 0.f, p1 = 0.f, p2 = 0.f;
    for (int k = tid; k < MLPD; k += 128) {
        float xv = g_x2[b][k];
        p0 = __fmaf_rn(xv, Wout[k * NC + 0], p0);
        p1 = __fmaf_rn(xv, Wout[k * NC + 1], p1);
        p2 = __fmaf_rn(xv, Wout[k * NC + 2], p2);
    }
    for (int o = 16; o; o >>= 1) {
        p0 += __shfl_xor_sync(0xffffffffu, p0, o);
        p1 += __shfl_xor_sync(0xffffffffu, p1, o);
        p2 += __shfl_xor_sync(0xffffffffu, p2, o);
    }
    int lane = tid & 31, wrp = tid >> 5;
    if (lane == 0) { red[wrp][0] = p0; red[wrp][1] = p1; red[wrp][2] = p2; }
    __syncthreads();
    if (tid < NC) {
        float s = bout[tid];
        for (int w = 0; w < 4; w++) s += red[w][tid];
        out[b * NC + tid] = s;
    }
}

// ======================================================================
extern "C" void kernel_launch(void* const* d_in, const int* in_sizes, int n_in,
                              void* d_out, int out_size) {
    const int*   sent = (const int*)d_in[0];
    // d_in[1] = transitions (unused by reference)
    const float* emb  = (const float*)d_in[2];
    const float* Wenc = (const float*)d_in[3];
    const float* benc = (const float*)d_in[4];
    const float* Wc   = (const float*)d_in[5];
    const float* bc   = (const float*)d_in[6];
    const float* Ws1  = (const float*)d_in[7];
    const float* bs1  = (const float*)d_in[8];
    const float* Ws2  = (const float*)d_in[9];
    const float* bs2  = (const float*)d_in[10];
    const float* Wm1  = (const float*)d_in[11];
    const float* bm1  = (const float*)d_in[12];
    const float* Wm2  = (const float*)d_in[13];
    const float* bm2  = (const float*)d_in[14];
    const float* Wout = (const float*)d_in[15];
    const float* bout = (const float*)d_in[16];

    encode_kernel<<<768, 128>>>(sent, emb, Wenc, benc);
    initsel_kernel<<<dim3(6, 64), 128>>>(Ws1, bs1, Ws2, bs2);
    scan_kernel<<<64, TPB>>>(Wc, bc, Ws1, bs1, Ws2, bs2);
    mlp_l1<<<dim3(4, B), 256>>>(Wm1, bm1);
    mlp_l2<<<dim3(4, B), 256>>>(Wm2, bm2);
    mlp_l3<<<B, 128>>>(Wout, bout, (float*)d_out);
}

// round 8
// speedup vs baseline: 1.4332x; 1.4332x over previous
#include <cuda_runtime.h>
#include <math.h>

#define B   64
#define S   96
#define E   300
#define D   512
#define H   256
#define SEL 128
#define G5  1280
#define MLPD 1024
#define NC  3

#define CL  8      // cluster size
#define NB  8      // batches per cluster
#define TPB 640

typedef unsigned long long ull;

__device__ __align__(16) float g_states[B][S][D];
__device__ float g_logits0[B][S - 1];
__device__ float g_hroot[B][H];
__device__ float g_x1[B][MLPD];
__device__ float g_x2[B][MLPD];
__device__ float g_p5[B][2][CL];

__device__ __forceinline__ float sigf(float x) { return 1.0f / (1.0f + expf(-x)); }
__device__ __forceinline__ ull fma2(ull a, ull b, ull c) {
    ull d; asm("fma.rn.f32x2 %0, %1, %2, %3;" : "=l"(d) : "l"(a), "l"(b), "l"(c)); return d;
}
__device__ __forceinline__ ull add2(ull a, ull b) {
    ull d; asm("add.rn.f32x2 %0, %1, %2;" : "=l"(d) : "l"(a), "l"(b)); return d;
}
__device__ __forceinline__ ull pack2(float x, float y) {
    ull d; asm("mov.b64 %0, {%1, %2};" : "=l"(d) : "f"(x), "f"(y)); return d;
}
__device__ __forceinline__ float lo32(ull v) { return __uint_as_float((unsigned)v); }
__device__ __forceinline__ float hi32(ull v) { return __uint_as_float((unsigned)(v >> 32)); }

__device__ __forceinline__ void cluster_sync_full() {
    asm volatile("fence.acq_rel.cluster;" ::: "memory");
    asm volatile("barrier.cluster.arrive.aligned;" ::: "memory");
    asm volatile("barrier.cluster.wait.aligned;" ::: "memory");
    asm volatile("fence.acq_rel.cluster;" ::: "memory");
}

// ---- dynamic smem layout (bytes) ----
#define O_XS2   0        // ull xs2[8][512]          32768
#define O_XP    32768    // ull xp[8][512]           32768
#define O_REDK  65536    // ull redk[20*8][16]       20480
#define O_P5Q   86016    // ull p5q[512]             4096
#define O_WS1S  90112    // float Ws1s[16][524]      33536
#define O_BCS   123648   // float bcs[160]           640
#define O_LG    124288   // float lg[8][96]          3072
#define O_PM    127360   // int pm[8][96]            3072
#define O_MISC  130432   // ints/floats              512
#define SMEM_SZ 131072

// ======================================================================
__global__ void encode_kernel(const int* __restrict__ sent, const float* __restrict__ emb,
                              const float* __restrict__ Wenc, const float* __restrict__ benc) {
    __shared__ float xsh[8][E];
    __shared__ int tok[8];
    int row0 = blockIdx.x * 8, tid = threadIdx.x;
    if (tid < 8) tok[tid] = sent[row0 + tid];
    __syncthreads();
    for (int i = tid; i < 8 * E; i += 128) {
        int r = i / E, k = i - r * E;
        xsh[r][k] = emb[(long)tok[r] * E + k];
    }
    __syncthreads();
    int c = tid * 4;
    float4 acc[8];
#pragma unroll
    for (int r = 0; r < 8; r++) acc[r] = make_float4(0.f, 0.f, 0.f, 0.f);
    for (int k = 0; k < E; k++) {
        float4 w = *(const float4*)&Wenc[k * D + c];
#pragma unroll
        for (int r = 0; r < 8; r++) {
            float xv = xsh[r][k];
            acc[r].x = __fmaf_rn(xv, w.x, acc[r].x); acc[r].y = __fmaf_rn(xv, w.y, acc[r].y);
            acc[r].z = __fmaf_rn(xv, w.z, acc[r].z); acc[r].w = __fmaf_rn(xv, w.w, acc[r].w);
        }
    }
    float4 bv = *(const float4*)&benc[c];
#pragma unroll
    for (int r = 0; r < 8; r++) {
        acc[r].x += bv.x; acc[r].y += bv.y; acc[r].z += bv.z; acc[r].w += bv.w;
        int gr = row0 + r, b = gr / S, s = gr - b * S;
        *(float4*)&g_states[b][s][c] = acc[r];
    }
}

// ======================================================================
__global__ void initsel_kernel(const float* __restrict__ Ws1, const float* __restrict__ bs1,
                               const float* __restrict__ Ws2, const float* __restrict__ bs2) {
    __shared__ float hs[17][H];
    __shared__ float red[4];
    int b = blockIdx.y, p0 = blockIdx.x * 16, tid = threadIdx.x;
    int nrows = min(17, S - p0);
    for (int i = tid; i < nrows * H; i += 128) {
        int r = i >> 8, k = i & (H - 1);
        hs[r][k] = g_states[b][p0 + r][H + k];
    }
    __syncthreads();
    int npairs = min(16, (S - 1) - p0);
    for (int p = 0; p < npairs; p++) {
        float a[8];
#pragma unroll
        for (int m = 0; m < 8; m++) a[m] = 0.0f;
        const float* wp = Ws1 + tid;
        for (int k = 0; k < 64; k++) {
#pragma unroll
            for (int m = 0; m < 4; m++)
                a[m] = __fmaf_rn(hs[p][m * 64 + k], wp[(m * 64 + k) * SEL], a[m]);
#pragma unroll
            for (int m = 0; m < 4; m++)
                a[4 + m] = __fmaf_rn(hs[p + 1][m * 64 + k], wp[(256 + m * 64 + k) * SEL], a[4 + m]);
        }
        float s = a[0] + a[1] + a[2] + a[3] + a[4] + a[5] + a[6] + a[7] + bs1[tid];
        float y = tanhf(s) * Ws2[tid];
        for (int o = 16; o; o >>= 1) y += __shfl_xor_sync(0xffffffffu, y, o);
        if ((tid & 31) == 0) red[tid >> 5] = y;
        __syncthreads();
        if (tid == 0) g_logits0[b][p0 + p] = red[0] + red[1] + red[2] + red[3] + bs2[0];
        __syncthreads();
    }
}

// ======================================================================
// Scan: 64 CTAs = 8 clusters x 8. Cluster owns 8 batches.
// CTA r: gate cols h in [32r,32r+32) for all 5 gates; sel j in [16r,16r+16).
// ======================================================================
__global__ void __cluster_dims__(CL, 1, 1) __launch_bounds__(TPB, 1)
scan_kernel(const float* __restrict__ Wc,  const float* __restrict__ bc,
            const float* __restrict__ Ws1, const float* __restrict__ bs1,
            const float* __restrict__ Ws2, const float* __restrict__ bs2) {
    extern __shared__ char dsm[];
    ull*   xs2  = (ull*)(dsm + O_XS2);
    ull*   xp   = (ull*)(dsm + O_XP);
    ull*   redk = (ull*)(dsm + O_REDK);
    ull*   p5q  = (ull*)(dsm + O_P5Q);
    float* Ws1s = (float*)(dsm + O_WS1S);
    float* bcs  = (float*)(dsm + O_BCS);
    float* lg   = (float*)(dsm + O_LG);
    int*   pmi  = (int*)(dsm + O_PM);
    int*   misc = (int*)(dsm + O_MISC);
    int* selidx = misc;        int* sLa = misc + 8;   int* sRa = misc + 16;
    float* amaxv = (float*)(misc + 24);               // [8][2]
    int*   amaxi = misc + 40;                          // [8][2]
    float* bs1s  = (float*)(misc + 56);                // [16]
    float* ws2s  = (float*)(misc + 72);                // [16]

    int tid = threadIdx.x;
    int r   = blockIdx.x & (CL - 1);
    int gb0 = (blockIdx.x >> 3) * NB;

    // ---- one-time preloads ----
    for (int i = tid; i < 512 * 16; i += TPB) {
        int k = i >> 4, j16 = i & 15;
        Ws1s[j16 * 524 + k] = Ws1[(size_t)k * SEL + r * 16 + j16];
    }
    if (tid < 160) bcs[tid] = bc[(tid >> 5) * 256 + r * 32 + (tid & 31)];
    if (tid < 16) { bs1s[tid] = bs1[r * 16 + tid]; ws2s[tid] = Ws2[r * 16 + tid]; }
    for (int i = tid; i < NB * (S - 1); i += TPB) {
        int b = i / (S - 1), j = i - b * (S - 1);
        lg[b * 96 + j] = g_logits0[gb0 + b][j];
    }
    for (int i = tid; i < NB * S; i += TPB) {
        int b = i / S, j = i - b * S;
        pmi[b * 96 + j] = j;
    }
    float bs2v = bs2[0];
    __syncthreads();

    // compose thread geometry
    int wid = tid >> 5, lane = tid & 31;
    int cg  = wid % 5, ckb = wid / 5;          // gate, k-block
    int cks = lane >> 3, cu4 = lane & 7;       // k-slice, col-quad
    const float* wpc = Wc + cg * 256 + r * 32 + cu4 * 4;
    int ck0 = ckb * 128 + cks * 2;

    for (int t = 0; t < S - 1; t++) {
        int n = S - t, np = n - 1;

        // ---- argmax (replicated) ----
        if (tid < 256) {
            int b = tid >> 5, ln = tid & 31;
            float best = -1e30f; int bi = 0;
            for (int j = ln; j < np; j += 32) {
                float v = lg[b * 96 + j];
                if (v > best) { best = v; bi = j; }
            }
            for (int o = 16; o; o >>= 1) {
                float ov = __shfl_xor_sync(0xffffffffu, best, o);
                int   oi = __shfl_xor_sync(0xffffffffu, bi, o);
                if (ov > best || (ov == best && oi < bi)) { best = ov; bi = oi; }
            }
            if (ln == 0) {
                selidx[b] = bi;
                sLa[b] = pmi[b * 96 + bi];
                sRa[b] = pmi[b * 96 + bi + 1];
            }
        }
        __syncthreads();

        // ---- xs staging (packed (x,x)) ----
        for (int i = tid; i < NB * D; i += TPB) {
            int b = i >> 9, k = i & (D - 1);
            int slot = (k < H) ? sLa[b] : sRa[b];
            int col  = (k < H) ? (H + k) : k;
            float xv = g_states[gb0 + b][slot][col];
            xs2[b * 512 + k] = pack2(xv, xv);
        }
        cluster_sync_full();                                  // SYNC 0

        // ---- compose: each thread 4 cols x 8 batches x 32 k (interleaved) ----
        {
            ull acc[16];
#pragma unroll
            for (int i = 0; i < 16; i++) acc[i] = 0ull;
#pragma unroll 4
            for (int m = 0; m < 16; m++) {
                int k = ck0 + m * 8;
                ulonglong2 w0 = *(const ulonglong2*)(wpc + (size_t)k * G5);
                ulonglong2 w1 = *(const ulonglong2*)(wpc + (size_t)(k + 1) * G5);
#pragma unroll
                for (int b = 0; b < 8; b++) {
                    ulonglong2 xv = *(const ulonglong2*)&xs2[b * 512 + k];
                    acc[b * 2]     = fma2(w0.x, xv.x, acc[b * 2]);
                    acc[b * 2 + 1] = fma2(w0.y, xv.x, acc[b * 2 + 1]);
                    acc[b * 2]     = fma2(w1.x, xv.y, acc[b * 2]);
                    acc[b * 2 + 1] = fma2(w1.y, xv.y, acc[b * 2 + 1]);
                }
            }
            // reduce over cks (lanes xor 8, 16) — fixed order
#pragma unroll
            for (int i = 0; i < 16; i++) {
                acc[i] = add2(acc[i], __shfl_xor_sync(0xffffffffu, acc[i], 8));
                acc[i] = add2(acc[i], __shfl_xor_sync(0xffffffffu, acc[i], 16));
            }
            if (cks == 0) {
                ull* dst = &redk[(size_t)(wid * 8 + cu4) * 16];
#pragma unroll
                for (int i = 0; i < 16; i++) dst[i] = acc[i];
            }
        }
        __syncthreads();

        // ---- gate assembly + state write: h in [32r, 32r+32), 8 batches ----
        if (tid < 256) {
            int b = tid >> 5, u = tid & 31;
            int u4 = u >> 2, cp = (u >> 1) & 1, half = u & 1;
            float gate[5];
#pragma unroll
            for (int g = 0; g < 5; g++) {
                float s = 0.f;
#pragma unroll
                for (int kb = 0; kb < 4; kb++) {
                    ull v = redk[(size_t)((kb * 5 + g) * 8 + u4) * 16 + b * 2 + cp];
                    s += half ? hi32(v) : lo32(v);
                }
                gate[g] = s + bcs[g * 32 + u];
            }
            int gb = gb0 + b, h = r * 32 + u;
            float cl = g_states[gb][sLa[b]][h];
            float cr = g_states[gb][sRa[b]][h];
            float cc = sigf(gate[1]) * cl + sigf(gate[2]) * cr + sigf(gate[0]) * tanhf(gate[4]);
            float hp = sigf(gate[3]) * tanhf(cc);
            g_states[gb][sLa[b]][h]     = cc;
            g_states[gb][sLa[b]][H + h] = hp;
        }
        cluster_sync_full();                                  // SYNC 1

        // ---- shift pm / lg (replicated, 768 slots over 640 threads) ----
        {
            int i0 = tid, i1 = tid + TPB;
            int b0 = i0 / 96, j0 = i0 - b0 * 96;
            int pv0 = 0, wp0 = 0, wl0 = 0; float lv0 = 0.f;
            {
                int idx = selidx[b0];
                if (j0 >= idx + 1 && j0 <= n - 2) { pv0 = pmi[b0 * 96 + j0 + 1]; wp0 = 1; }
                if (j0 >= idx + 1 && j0 <= n - 3) { lv0 = lg[b0 * 96 + j0 + 1]; wl0 = 1; }
            }
            int b1 = 0, j1 = 0, pv1 = 0, wp1 = 0, wl1 = 0; float lv1 = 0.f;
            if (i1 < NB * 96) {
                b1 = i1 / 96; j1 = i1 - b1 * 96;
                int idx = selidx[b1];
                if (j1 >= idx + 1 && j1 <= n - 2) { pv1 = pmi[b1 * 96 + j1 + 1]; wp1 = 1; }
                if (j1 >= idx + 1 && j1 <= n - 3) { lv1 = lg[b1 * 96 + j1 + 1]; wl1 = 1; }
            }
            __syncthreads();
            if (wp0) pmi[b0 * 96 + j0] = pv0;
            if (wl0) lg[b0 * 96 + j0] = lv0;
            if (wp1) pmi[b1 * 96 + j1] = pv1;
            if (wl1) lg[b1 * 96 + j1] = lv1;
        }
        __syncthreads();

        // ---- xp staging: 8 batches x 2 new pairs, packed ----
        for (int i = tid; i < NB * D; i += TPB) {
            int b = i >> 9, k = i & (D - 1);
            int idx = selidx[b];
            int q0 = idx - 1, q1 = idx;
            int col = (k < H) ? (H + k) : k;
            float xA = 0.f, xB = 0.f;
            if (q0 >= 0 && q0 <= n - 3)
                xA = g_states[gb0 + b][(k < H) ? pmi[b * 96 + q0] : pmi[b * 96 + q0 + 1]][col];
            if (q1 <= n - 3)
                xB = g_states[gb0 + b][(k < H) ? pmi[b * 96 + q1] : pmi[b * 96 + q1 + 1]][col];
            xp[b * 512 + k] = pack2(xA, xB);
        }
        __syncthreads();

        // ---- phase5 partials: own j-slice, all 8 batches, both pairs ----
        if (tid < 512) {
            int j16 = tid & 15, b = (tid >> 4) & 7, kh = tid >> 7;
            const float* wr = Ws1s + j16 * 524 + kh * 128;
            const ull*   xr = xp + b * 512 + kh * 128;
            ull a0 = 0ull, a1 = 0ull;
#pragma unroll 8
            for (int m = 0; m < 32; m++) {
                float4 wv = *(const float4*)(wr + m * 4);
                ulonglong2 x01 = *(const ulonglong2*)(xr + m * 4);
                ulonglong2 x23 = *(const ulonglong2*)(xr + m * 4 + 2);
                a0 = fma2(pack2(wv.x, wv.x), x01.x, a0);
                a1 = fma2(pack2(wv.y, wv.y), x01.y, a1);
                a0 = fma2(pack2(wv.z, wv.z), x23.x, a0);
                a1 = fma2(pack2(wv.w, wv.w), x23.y, a1);
            }
            p5q[tid] = add2(a0, a1);     // index = kh*128 + b*16 + j16
        }
        __syncthreads();
        if (tid < 128) {
            int j16 = tid & 15, b = tid >> 4;
            ull v = p5q[tid];
            v = add2(v, p5q[128 + tid]); v = add2(v, p5q[256 + tid]); v = add2(v, p5q[384 + tid]);
            float sA = lo32(v) + bs1s[j16], sB = hi32(v) + bs1s[j16];
            float yA = tanhf(sA) * ws2s[j16];
            float yB = tanhf(sB) * ws2s[j16];
#pragma unroll
            for (int o = 1; o < 16; o <<= 1) {
                yA += __shfl_xor_sync(0xffffffffu, yA, o);
                yB += __shfl_xor_sync(0xffffffffu, yB, o);
            }
            if (j16 == 0) { g_p5[gb0 + b][0][r] = yA; g_p5[gb0 + b][1][r] = yB; }
        }
        cluster_sync_full();                                  // SYNC 2

        // ---- lg update from rank partials (ordered, replicated) ----
        if (tid < 16) {
            int b = tid >> 1, s = tid & 1;
            int q = selidx[b] - 1 + s;
            if (q >= 0 && q <= n - 3) {
                float v = bs2v;
#pragma unroll
                for (int rr = 0; rr < CL; rr++) v += g_p5[gb0 + b][s][rr];
                lg[b * 96 + q] = v;
            }
        }
        __syncthreads();
    }

    // ---- root hidden: own h-slice, 8 batches ----
    if (tid < 256) {
        int b = tid >> 5, u = tid & 31;
        g_hroot[gb0 + b][r * 32 + u] = g_states[gb0 + b][pmi[b * 96]][H + r * 32 + u];
    }
}

// ======================================================================
__global__ void mlp_l1(const float* __restrict__ Wm1, const float* __restrict__ bm1) {
    __shared__ float hsh[H];
    int b = blockIdx.y, c = blockIdx.x * 256 + threadIdx.x;
    if (threadIdx.x < H) hsh[threadIdx.x] = g_hroot[b][threadIdx.x];
    __syncthreads();
    float acc = bm1[c];
    const float* wp = Wm1 + c;
#pragma unroll 8
    for (int k = 0; k < H; k++) acc = __fmaf_rn(hsh[k], wp[k * MLPD], acc);
    g_x1[b][c] = fmaxf(acc, 0.0f);
}

__global__ void mlp_l2(const float* __restrict__ Wm2, const float* __restrict__ bm2) {
    __shared__ float x1s[MLPD];
    int b = blockIdx.y, c = blockIdx.x * 256 + threadIdx.x;
    for (int i = threadIdx.x; i < MLPD; i += 256) x1s[i] = g_x1[b][i];
    __syncthreads();
    float acc = bm2[c];
    const float* wp = Wm2 + c;
#pragma unroll 8
    for (int k = 0; k < MLPD; k++) acc = __fmaf_rn(x1s[k], wp[k * MLPD], acc);
    g_x2[b][c] = fmaxf(acc, 0.0f);
}

__global__ void mlp_l3(const float* __restrict__ Wout, const float* __restrict__ bout,
                       float* __restrict__ out) {
    __shared__ float red[4][NC];
    int b = blockIdx.x, tid = threadIdx.x;
    float p0 = 0.f, p1 = 0.f, p2 = 0.f;
    for (int k = tid; k < MLPD; k += 128) {
        float xv = g_x2[b][k];
        p0 = __fmaf_rn(xv, Wout[k * NC + 0], p0);
        p1 = __fmaf_rn(xv, Wout[k * NC + 1], p1);
        p2 = __fmaf_rn(xv, Wout[k * NC + 2], p2);
    }
    for (int o = 16; o; o >>= 1) {
        p0 += __shfl_xor_sync(0xffffffffu, p0, o);
        p1 += __shfl_xor_sync(0xffffffffu, p1, o);
        p2 += __shfl_xor_sync(0xffffffffu, p2, o);
    }
    int lane = tid & 31, wrp = tid >> 5;
    if (lane == 0) { red[wrp][0] = p0; red[wrp][1] = p1; red[wrp][2] = p2; }
    __syncthreads();
    if (tid < NC) {
        float s = bout[tid];
        for (int w = 0; w < 4; w++) s += red[w][tid];
        out[b * NC + tid] = s;
    }
}

// ======================================================================
extern "C" void kernel_launch(void* const* d_in, const int* in_sizes, int n_in,
                              void* d_out, int out_size) {
    const int*   sent = (const int*)d_in[0];
    const float* emb  = (const float*)d_in[2];
    const float* Wenc = (const float*)d_in[3];
    const float* benc = (const float*)d_in[4];
    const float* Wc   = (const float*)d_in[5];
    const float* bc   = (const float*)d_in[6];
    const float* Ws1  = (const float*)d_in[7];
    const float* bs1  = (const float*)d_in[8];
    const float* Ws2  = (const float*)d_in[9];
    const float* bs2  = (const float*)d_in[10];
    const float* Wm1  = (const float*)d_in[11];
    const float* bm1  = (const float*)d_in[12];
    const float* Wm2  = (const float*)d_in[13];
    const float* bm2  = (const float*)d_in[14];
    const float* Wout = (const float*)d_in[15];
    const float* bout = (const float*)d_in[16];

    static int smem_set = 0;
    if (!smem_set) {
        cudaFuncSetAttribute(scan_kernel, cudaFuncAttributeMaxDynamicSharedMemorySize, SMEM_SZ);
        smem_set = 1;
    }

    encode_kernel<<<768, 128>>>(sent, emb, Wenc, benc);
    initsel_kernel<<<dim3(6, 64), 128>>>(Ws1, bs1, Ws2, bs2);
    scan_kernel<<<64, TPB, SMEM_SZ>>>(Wc, bc, Ws1, bs1, Ws2, bs2);
    mlp_l1<<<dim3(4, B), 256>>>(Wm1, bm1);
    mlp_l2<<<dim3(4, B), 256>>>(Wm2, bm2);
    mlp_l3<<<B, 128>>>(Wout, bout, (float*)d_out);
}

// round 9
// speedup vs baseline: 1.4950x; 1.0431x over previous
#include <cuda_runtime.h>
#include <math.h>

#define B   64
#define S   96
#define E   300
#define H   256
#define D   512
#define SEL 128
#define G5  1280
#define MLPD 1024
#define NC  3

#define CL  8      // cluster size
#define NB  8      // batches per cluster
#define TPB 640
#define NS  97     // S + 1 spare slot per batch

typedef unsigned long long ull;

__device__ __align__(16) float g_states[B][NS][D];
__device__ float g_logits0[B][S - 1];
__device__ float g_hroot[B][H];
__device__ float g_x1[B][MLPD];
__device__ float g_x2[B][MLPD];
__device__ float g_p5[B][2][CL];

__device__ __forceinline__ float sigf(float x) { return 1.0f / (1.0f + expf(-x)); }
__device__ __forceinline__ ull fma2(ull a, ull b, ull c) {
    ull d; asm("fma.rn.f32x2 %0, %1, %2, %3;" : "=l"(d) : "l"(a), "l"(b), "l"(c)); return d;
}
__device__ __forceinline__ ull add2(ull a, ull b) {
    ull d; asm("add.rn.f32x2 %0, %1, %2;" : "=l"(d) : "l"(a), "l"(b)); return d;
}
__device__ __forceinline__ ull pack2(float x, float y) {
    ull d; asm("mov.b64 %0, {%1, %2};" : "=l"(d) : "f"(x), "f"(y)); return d;
}
__device__ __forceinline__ float lo32(ull v) { return __uint_as_float((unsigned)v); }
__device__ __forceinline__ float hi32(ull v) { return __uint_as_float((unsigned)(v >> 32)); }

// release-arrive / acquire-wait cluster barrier: orders weak STG (to L2)
// against peers' __ldcg (from L2) without any CCTL.IVALL L1 flush.
__device__ __forceinline__ void cluster_bar() {
    asm volatile("barrier.cluster.arrive.release.aligned;" ::: "memory");
    asm volatile("barrier.cluster.wait.acquire.aligned;" ::: "memory");
}

// ---- dynamic smem layout (bytes) ----
#define O_XS2   0        // ull xs2[8][512]          32768
#define O_XP    32768    // ull xp[8][512]           32768
#define O_REDK  65536    // ull redk[20*8][16]       20480
#define O_P5Q   86016    // ull p5q[512]             4096
#define O_WS1S  90112    // float Ws1s[16][524]      33536
#define O_BCS   123648   // float bcs[160]           640
#define O_LG    124288   // float lg[8][96]          3072
#define O_PM    127360   // int pm[8][96]            3072
#define O_MISC  130432   // ints/floats              512
#define O_CLCR  130944   // float clcr[8][2][32]     2048
#define SMEM_SZ 132992

// ======================================================================
__global__ void encode_kernel(const int* __restrict__ sent, const float* __restrict__ emb,
                              const float* __restrict__ Wenc, const float* __restrict__ benc) {
    __shared__ float xsh[8][E];
    __shared__ int tok[8];
    int row0 = blockIdx.x * 8, tid = threadIdx.x;
    if (tid < 8) tok[tid] = sent[row0 + tid];
    __syncthreads();
    for (int i = tid; i < 8 * E; i += 128) {
        int r = i / E, k = i - r * E;
        xsh[r][k] = emb[(long)tok[r] * E + k];
    }
    __syncthreads();
    int c = tid * 4;
    float4 acc[8];
#pragma unroll
    for (int r = 0; r < 8; r++) acc[r] = make_float4(0.f, 0.f, 0.f, 0.f);
    for (int k = 0; k < E; k++) {
        float4 w = *(const float4*)&Wenc[k * D + c];
#pragma unroll
        for (int r = 0; r < 8; r++) {
            float xv = xsh[r][k];
            acc[r].x = __fmaf_rn(xv, w.x, acc[r].x); acc[r].y = __fmaf_rn(xv, w.y, acc[r].y);
            acc[r].z = __fmaf_rn(xv, w.z, acc[r].z); acc[r].w = __fmaf_rn(xv, w.w, acc[r].w);
        }
    }
    float4 bv = *(const float4*)&benc[c];
#pragma unroll
    for (int r = 0; r < 8; r++) {
        acc[r].x += bv.x; acc[r].y += bv.y; acc[r].z += bv.z; acc[r].w += bv.w;
        int gr = row0 + r, b = gr / S, s = gr - b * S;
        *(float4*)&g_states[b][s][c] = acc[r];
    }
}

// ======================================================================
__global__ void initsel_kernel(const float* __restrict__ Ws1, const float* __restrict__ bs1,
                               const float* __restrict__ Ws2, const float* __restrict__ bs2) {
    __shared__ float hs[17][H];
    __shared__ float red[4];
    int b = blockIdx.y, p0 = blockIdx.x * 16, tid = threadIdx.x;
    int nrows = min(17, S - p0);
    for (int i = tid; i < nrows * H; i += 128) {
        int r = i >> 8, k = i & (H - 1);
        hs[r][k] = g_states[b][p0 + r][H + k];
    }
    __syncthreads();
    int npairs = min(16, (S - 1) - p0);
    for (int p = 0; p < npairs; p++) {
        float a[8];
#pragma unroll
        for (int m = 0; m < 8; m++) a[m] = 0.0f;
        const float* wp = Ws1 + tid;
        for (int k = 0; k < 64; k++) {
#pragma unroll
            for (int m = 0; m < 4; m++)
                a[m] = __fmaf_rn(hs[p][m * 64 + k], wp[(m * 64 + k) * SEL], a[m]);
#pragma unroll
            for (int m = 0; m < 4; m++)
                a[4 + m] = __fmaf_rn(hs[p + 1][m * 64 + k], wp[(256 + m * 64 + k) * SEL], a[4 + m]);
        }
        float s = a[0] + a[1] + a[2] + a[3] + a[4] + a[5] + a[6] + a[7] + bs1[tid];
        float y = tanhf(s) * Ws2[tid];
        for (int o = 16; o; o >>= 1) y += __shfl_xor_sync(0xffffffffu, y, o);
        if ((tid & 31) == 0) red[tid >> 5] = y;
        __syncthreads();
        if (tid == 0) g_logits0[b][p0 + p] = red[0] + red[1] + red[2] + red[3] + bs2[0];
        __syncthreads();
    }
}

// ======================================================================
// Scan: 64 CTAs = 8 clusters x 8, 8 batches/cluster.
// CTA r: gate cols h in [32r,32r+32); sel j in [16r,16r+16).
// Fresh-slot writes => only 2 cluster barriers per step.
// ======================================================================
__global__ void __cluster_dims__(CL, 1, 1) __launch_bounds__(TPB, 1)
scan_kernel(const float* __restrict__ Wc,  const float* __restrict__ bc,
            const float* __restrict__ Ws1, const float* __restrict__ bs1,
            const float* __restrict__ Ws2, const float* __restrict__ bs2) {
    extern __shared__ char dsm[];
    ull*   xs2  = (ull*)(dsm + O_XS2);
    ull*   xp   = (ull*)(dsm + O_XP);
    ull*   redk = (ull*)(dsm + O_REDK);
    ull*   p5q  = (ull*)(dsm + O_P5Q);
    float* Ws1s = (float*)(dsm + O_WS1S);
    float* bcs  = (float*)(dsm + O_BCS);
    float* lg   = (float*)(dsm + O_LG);
    int*   pmi  = (int*)(dsm + O_PM);
    int*   misc = (int*)(dsm + O_MISC);
    float* clcr = (float*)(dsm + O_CLCR);   // [8][2][32]
    int* selidx = misc;        int* sLa = misc + 8;   int* sRa = misc + 16;
    int* frs    = misc + 24;   int* fsl = misc + 32;  // free-slot chain
    float* bs1s = (float*)(misc + 40);                 // [16]
    float* ws2s = (float*)(misc + 56);                 // [16]

    int tid = threadIdx.x;
    int r   = blockIdx.x & (CL - 1);
    int gb0 = (blockIdx.x >> 3) * NB;

    // ---- one-time preloads ----
    for (int i = tid; i < 512 * 16; i += TPB) {
        int k = i >> 4, j16 = i & 15;
        Ws1s[j16 * 524 + k] = Ws1[(size_t)k * SEL + r * 16 + j16];
    }
    if (tid < 160) bcs[tid] = bc[(tid >> 5) * 256 + r * 32 + (tid & 31)];
    if (tid < 16) { bs1s[tid] = bs1[r * 16 + tid]; ws2s[tid] = Ws2[r * 16 + tid]; }
    if (tid < 8)  frs[tid] = 96;   // spare slot per batch
    for (int i = tid; i < NB * (S - 1); i += TPB) {
        int b = i / (S - 1), j = i - b * (S - 1);
        lg[b * 96 + j] = g_logits0[gb0 + b][j];
    }
    for (int i = tid; i < NB * S; i += TPB) {
        int b = i / S, j = i - b * S;
        pmi[b * 96 + j] = j;
    }
    float bs2v = bs2[0];
    __syncthreads();

    // compose geometry
    int wid = tid >> 5, lane = tid & 31;
    int cg  = wid % 5, ckb = wid / 5;
    int cks = lane >> 3, cu4 = lane & 7;
    const float* wpc = Wc + cg * 256 + r * 32 + cu4 * 4;
    int ck0 = ckb * 128 + cks * 2;

    for (int t = 0; t < S - 1; t++) {
        int n = S - t, np = n - 1;

        // ---- argmax (replicated) + free-slot bookkeeping ----
        if (tid < 256) {
            int b = tid >> 5, ln = tid & 31;
            float best = -1e30f; int bi = 0;
            for (int j = ln; j < np; j += 32) {
                float v = lg[b * 96 + j];
                if (v > best) { best = v; bi = j; }
            }
            for (int o = 16; o; o >>= 1) {
                float ov = __shfl_xor_sync(0xffffffffu, best, o);
                int   oi = __shfl_xor_sync(0xffffffffu, bi, o);
                if (ov > best || (ov == best && oi < bi)) { best = ov; bi = oi; }
            }
            if (ln == 0) {
                int sl = pmi[b * 96 + bi], sr = pmi[b * 96 + bi + 1];
                selidx[b] = bi; sLa[b] = sl; sRa[b] = sr;
                fsl[b] = frs[b];      // fresh slot this step (dead slot)
                frs[b] = sr;          // sR dies after this step
            }
        }
        __syncthreads();

        // ---- staging: xs2 (packed (x,x)) + clcr (cl/cr for own h-slice) ----
        for (int i = tid; i < NB * D; i += TPB) {
            int b = i >> 9, k = i & (D - 1);
            int slot = (k < H) ? sLa[b] : sRa[b];
            int col  = (k < H) ? (H + k) : k;
            float xv = __ldcg(&g_states[gb0 + b][slot][col]);
            xs2[b * 512 + k] = pack2(xv, xv);
        }
        if (tid < 512) {
            int b = tid >> 6, half = (tid >> 5) & 1, u = tid & 31;
            clcr[(b * 2 + half) * 32 + u] =
                __ldcg(&g_states[gb0 + b][half ? sRa[b] : sLa[b]][r * 32 + u]);
        }
        __syncthreads();

        // ---- compose ----
        {
            ull acc[16];
#pragma unroll
            for (int i = 0; i < 16; i++) acc[i] = 0ull;
#pragma unroll 4
            for (int m = 0; m < 16; m++) {
                int k = ck0 + m * 8;
                ulonglong2 w0 = *(const ulonglong2*)(wpc + (size_t)k * G5);
                ulonglong2 w1 = *(const ulonglong2*)(wpc + (size_t)(k + 1) * G5);
#pragma unroll
                for (int b = 0; b < 8; b++) {
                    ulonglong2 xv = *(const ulonglong2*)&xs2[b * 512 + k];
                    acc[b * 2]     = fma2(w0.x, xv.x, acc[b * 2]);
                    acc[b * 2 + 1] = fma2(w0.y, xv.x, acc[b * 2 + 1]);
                    acc[b * 2]     = fma2(w1.x, xv.y, acc[b * 2]);
                    acc[b * 2 + 1] = fma2(w1.y, xv.y, acc[b * 2 + 1]);
                }
            }
#pragma unroll
            for (int i = 0; i < 16; i++) {
                acc[i] = add2(acc[i], __shfl_xor_sync(0xffffffffu, acc[i], 8));
                acc[i] = add2(acc[i], __shfl_xor_sync(0xffffffffu, acc[i], 16));
            }
            if (cks == 0) {
                ull* dst = &redk[(size_t)(wid * 8 + cu4) * 16];
#pragma unroll
                for (int i = 0; i < 16; i++) dst[i] = acc[i];
            }
        }
        __syncthreads();

        // ---- gates (tid<256) overlapped with shift-read (tid>=256) ----
        int spv0 = 0, swp0 = 0, swl0 = 0; float slv0 = 0.f; int sb0 = 0, sj0 = 0;
        int spv1 = 0, swp1 = 0, swl1 = 0; float slv1 = 0.f; int sb1 = 0, sj1 = 0;
        if (tid < 256) {
            int b = tid >> 5, u = tid & 31;
            int u4 = u >> 2, cp = (u >> 1) & 1, half = u & 1;
            float gate[5];
#pragma unroll
            for (int g = 0; g < 5; g++) {
                float s = 0.f;
#pragma unroll
                for (int kb = 0; kb < 4; kb++) {
                    ull v = redk[(size_t)((kb * 5 + g) * 8 + u4) * 16 + b * 2 + cp];
                    s += half ? hi32(v) : lo32(v);
                }
                gate[g] = s + bcs[g * 32 + u];
            }
            int gb = gb0 + b, h = r * 32 + u;
            float cl = clcr[(b * 2 + 0) * 32 + u];
            float cr = clcr[(b * 2 + 1) * 32 + u];
            float cc = sigf(gate[1]) * cl + sigf(gate[2]) * cr + sigf(gate[0]) * tanhf(gate[4]);
            float hp = sigf(gate[3]) * tanhf(cc);
            g_states[gb][fsl[b]][h]     = cc;      // write to FRESH slot
            g_states[gb][fsl[b]][H + h] = hp;
        } else {
            int ii0 = tid - 256, ii1 = ii0 + 384;
            sb0 = ii0 / 96; sj0 = ii0 - sb0 * 96;
            {
                int idx = selidx[sb0];
                if (sj0 >= idx + 1 && sj0 <= n - 2) { spv0 = pmi[sb0 * 96 + sj0 + 1]; swp0 = 1; }
                if (sj0 >= idx + 1 && sj0 <= n - 3) { slv0 = lg[sb0 * 96 + sj0 + 1]; swl0 = 1; }
            }
            if (ii1 < NB * 96) {
                sb1 = ii1 / 96; sj1 = ii1 - sb1 * 96;
                int idx = selidx[sb1];
                if (sj1 >= idx + 1 && sj1 <= n - 2) { spv1 = pmi[sb1 * 96 + sj1 + 1]; swp1 = 1; }
                if (sj1 >= idx + 1 && sj1 <= n - 3) { slv1 = lg[sb1 * 96 + sj1 + 1]; swl1 = 1; }
            }
        }
        __syncthreads();
        if (tid >= 256) {
            if (swp0) pmi[sb0 * 96 + sj0] = spv0;
            if (swl0) lg[sb0 * 96 + sj0] = slv0;
            if (swp1) pmi[sb1 * 96 + sj1] = spv1;
            if (swl1) lg[sb1 * 96 + sj1] = slv1;
        }
        if (tid < 8) pmi[tid * 96 + selidx[tid]] = fsl[tid];   // merged -> fresh slot
        cluster_bar();                                          // SYNC1: fresh state visible

        // ---- xp staging: 8 batches x 2 new pairs ----
        for (int i = tid; i < NB * D; i += TPB) {
            int b = i >> 9, k = i & (D - 1);
            int idx = selidx[b];
            int q0 = idx - 1, q1 = idx;
            int col = (k < H) ? (H + k) : k;
            float xA = 0.f, xB = 0.f;
            if (q0 >= 0 && q0 <= n - 3)
                xA = __ldcg(&g_states[gb0 + b][(k < H) ? pmi[b * 96 + q0] : pmi[b * 96 + q0 + 1]][col]);
            if (q1 <= n - 3)
                xB = __ldcg(&g_states[gb0 + b][(k < H) ? pmi[b * 96 + q1] : pmi[b * 96 + q1 + 1]][col]);
            xp[b * 512 + k] = pack2(xA, xB);
        }
        __syncthreads();

        // ---- phase5 partials (smem weights) ----
        if (tid < 512) {
            int j16 = tid & 15, b = (tid >> 4) & 7, kh = tid >> 7;
            const float* wr = Ws1s + j16 * 524 + kh * 128;
            const ull*   xr = xp + b * 512 + kh * 128;
            ull a0 = 0ull, a1 = 0ull;
#pragma unroll 8
            for (int m = 0; m < 32; m++) {
                float4 wv = *(const float4*)(wr + m * 4);
                ulonglong2 x01 = *(const ulonglong2*)(xr + m * 4);
                ulonglong2 x23 = *(const ulonglong2*)(xr + m * 4 + 2);
                a0 = fma2(pack2(wv.x, wv.x), x01.x, a0);
                a1 = fma2(pack2(wv.y, wv.y), x01.y, a1);
                a0 = fma2(pack2(wv.z, wv.z), x23.x, a0);
                a1 = fma2(pack2(wv.w, wv.w), x23.y, a1);
            }
            p5q[tid] = add2(a0, a1);
        }
        __syncthreads();
        if (tid < 128) {
            int j16 = tid & 15, b = tid >> 4;
            ull v = p5q[tid];
            v = add2(v, p5q[128 + tid]); v = add2(v, p5q[256 + tid]); v = add2(v, p5q[384 + tid]);
            float sA = lo32(v) + bs1s[j16], sB = hi32(v) + bs1s[j16];
            float yA = tanhf(sA) * ws2s[j16];
            float yB = tanhf(sB) * ws2s[j16];
#pragma unroll
            for (int o = 1; o < 16; o <<= 1) {
                yA += __shfl_xor_sync(0xffffffffu, yA, o);
                yB += __shfl_xor_sync(0xffffffffu, yB, o);
            }
            if (j16 == 0) { g_p5[gb0 + b][0][r] = yA; g_p5[gb0 + b][1][r] = yB; }
        }
        cluster_bar();                                          // SYNC2: partials visible

        // ---- lg update (ordered rank sum, replicated) ----
        if (tid < 16) {
            int b = tid >> 1, s = tid & 1;
            int q = selidx[b] - 1 + s;
            if (q >= 0 && q <= n - 3) {
                float v = bs2v;
#pragma unroll
                for (int rr = 0; rr < CL; rr++) v += __ldcg(&g_p5[gb0 + b][s][rr]);
                lg[b * 96 + q] = v;
            }
        }
        __syncthreads();
    }

    // ---- root hidden ----
    if (tid < 256) {
        int b = tid >> 5, u = tid & 31;
        g_hroot[gb0 + b][r * 32 + u] = __ldcg(&g_states[gb0 + b][pmi[b * 96]][H + r * 32 + u]);
    }
}

// ======================================================================
__global__ void mlp_l1(const float* __restrict__ Wm1, const float* __restrict__ bm1) {
    __shared__ float hsh[H];
    int b = blockIdx.y, c = blockIdx.x * 256 + threadIdx.x;
    if (threadIdx.x < H) hsh[threadIdx.x] = g_hroot[b][threadIdx.x];
    __syncthreads();
    float acc = bm1[c];
    const float* wp = Wm1 + c;
#pragma unroll 8
    for (int k = 0; k < H; k++) acc = __fmaf_rn(hsh[k], wp[k * MLPD], acc);
    g_x1[b][c] = fmaxf(acc, 0.0f);
}

__global__ void mlp_l2(const float* __restrict__ Wm2, const float* __restrict__ bm2) {
    __shared__ float x1s[MLPD];
    int b = blockIdx.y, c = blockIdx.x * 256 + threadIdx.x;
    for (int i = threadIdx.x; i < MLPD; i += 256) x1s[i] = g_x1[b][i];
    __syncthreads();
    float acc = bm2[c];
    const float* wp = Wm2 + c;
#pragma unroll 8
    for (int k = 0; k < MLPD; k++) acc = __fmaf_rn(x1s[k], wp[k * MLPD], acc);
    g_x2[b][c] = fmaxf(acc, 0.0f);
}

__global__ void mlp_l3(const float* __restrict__ Wout, const float* __restrict__ bout,
                       float* __restrict__ out) {
    __shared__ float red[4][NC];
    int b = blockIdx.x, tid = threadIdx.x;
    float p0 = 0.f, p1 = 0.f, p2 = 0.f;
    for (int k = tid; k < MLPD; k += 128) {
        float xv = g_x2[b][k];
        p0 = __fmaf_rn(xv, Wout[k * NC + 0], p0);
        p1 = __fmaf_rn(xv, Wout[k * NC + 1], p1);
        p2 = __fmaf_rn(xv, Wout[k * NC + 2], p2);
    }
    for (int o = 16; o; o >>= 1) {
        p0 += __shfl_xor_sync(0xffffffffu, p0, o);
        p1 += __shfl_xor_sync(0xffffffffu, p1, o);
        p2 += __shfl_xor_sync(0xffffffffu, p2, o);
    }
    int lane = tid & 31, wrp = tid >> 5;
    if (lane == 0) { red[wrp][0] = p0; red[wrp][1] = p1; red[wrp][2] = p2; }
    __syncthreads();
    if (tid < NC) {
        float s = bout[tid];
        for (int w = 0; w < 4; w++) s += red[w][tid];
        out[b * NC + tid] = s;
    }
}

// ======================================================================
extern "C" void kernel_launch(void* const* d_in, const int* in_sizes, int n_in,
                              void* d_out, int out_size) {
    const int*   sent = (const int*)d_in[0];
    const float* emb  = (const float*)d_in[2];
    const float* Wenc = (const float*)d_in[3];
    const float* benc = (const float*)d_in[4];
    const float* Wc   = (const float*)d_in[5];
    const float* bc   = (const float*)d_in[6];
    const float* Ws1  = (const float*)d_in[7];
    const float* bs1  = (const float*)d_in[8];
    const float* Ws2  = (const float*)d_in[9];
    const float* bs2  = (const float*)d_in[10];
    const float* Wm1  = (const float*)d_in[11];
    const float* bm1  = (const float*)d_in[12];
    const float* Wm2  = (const float*)d_in[13];
    const float* bm2  = (const float*)d_in[14];
    const float* Wout = (const float*)d_in[15];
    const float* bout = (const float*)d_in[16];

    static int smem_set = 0;
    if (!smem_set) {
        cudaFuncSetAttribute(scan_kernel, cudaFuncAttributeMaxDynamicSharedMemorySize, SMEM_SZ);
        smem_set = 1;
    }

    encode_kernel<<<768, 128>>>(sent, emb, Wenc, benc);
    initsel_kernel<<<dim3(6, 64), 128>>>(Ws1, bs1, Ws2, bs2);
    scan_kernel<<<64, TPB, SMEM_SZ>>>(Wc, bc, Ws1, bs1, Ws2, bs2);
    mlp_l1<<<dim3(4, B), 256>>>(Wm1, bm1);
    mlp_l2<<<dim3(4, B), 256>>>(Wm2, bm2);
    mlp_l3<<<B, 128>>>(Wout, bout, (float*)d_out);
}

// round 10
// speedup vs baseline: 1.5921x; 1.0649x over previous
#include <cuda_runtime.h>
#include <math.h>

#define B   64
#define S   96
#define E   300
#define H   256
#define D   512
#define SEL 128
#define G5  1280
#define MLPD 1024
#define NC  3

#define CL  8      // cluster size
#define NB  8      // batches per cluster
#define TPB 640
#define NS  97     // S + 1 spare slot per batch

typedef unsigned long long ull;

__device__ __align__(16) float g_states[B][NS][D];
__device__ float g_logits0[B][S - 1];
__device__ float g_hroot[B][H];
__device__ float g_x1[B][MLPD];
__device__ float g_x2[B][MLPD];

__device__ __forceinline__ float sigf(float x) { return 1.0f / (1.0f + expf(-x)); }
__device__ __forceinline__ ull fma2(ull a, ull b, ull c) {
    ull d; asm("fma.rn.f32x2 %0, %1, %2, %3;" : "=l"(d) : "l"(a), "l"(b), "l"(c)); return d;
}
__device__ __forceinline__ ull add2(ull a, ull b) {
    ull d; asm("add.rn.f32x2 %0, %1, %2;" : "=l"(d) : "l"(a), "l"(b)); return d;
}
__device__ __forceinline__ ull pack2(float x, float y) {
    ull d; asm("mov.b64 %0, {%1, %2};" : "=l"(d) : "f"(x), "f"(y)); return d;
}
__device__ __forceinline__ float lo32(ull v) { return __uint_as_float((unsigned)v); }
__device__ __forceinline__ float hi32(ull v) { return __uint_as_float((unsigned)(v >> 32)); }

__device__ __forceinline__ unsigned smem_u32(const void* p) {
    return (unsigned)__cvta_generic_to_shared(p);
}
// store f32 into the same smem offset of cluster CTA `rank`
__device__ __forceinline__ void stc_f32(unsigned laddr, int rank, float v) {
    unsigned ra;
    asm volatile("mapa.shared::cluster.u32 %0, %1, %2;" : "=r"(ra) : "r"(laddr), "r"(rank));
    asm volatile("st.shared::cluster.f32 [%0], %1;" :: "r"(ra), "f"(v));
}

// release/acquire cluster barrier (no L1 flush; DSMEM + L2 ordering)
__device__ __forceinline__ void cluster_bar() {
    asm volatile("barrier.cluster.arrive.release.aligned;" ::: "memory");
    asm volatile("barrier.cluster.wait.acquire.aligned;" ::: "memory");
}

// ---- dynamic smem layout (bytes) ----
#define O_XS2   0        // ull xs2[8][512]          32768
#define O_XP    32768    // ull xp[8][512]           32768
#define O_REDK  65536    // ull redk[20*8][16]       20480
#define O_P5Q   86016    // ull p5q[512]             4096
#define O_WS1S  90112    // float Ws1s[16][524]      33536
#define O_BCS   123648   // float bcs[160]           640
#define O_LG    124288   // float lg[8][96]          3072
#define O_PM    127360   // int pm[8][96]            3072
#define O_MISC  130432   // ints/floats              512
#define O_CLCR  130944   // float clcr[8][2][32]     2048
#define O_XNL   132992   // float xnl[8][256]        8192  (left-neighbor h)
#define O_XNR   141184   // float xnr[8][256]        8192  (right-neighbor h)
#define O_HM    149376   // float hM[8][256]         8192  (merged h', DSMEM bcast)
#define O_P5A   157568   // float p5all[8][16]       512   (rank partials, DSMEM)
#define SMEM_SZ 158080

// pad kernel: shifts ncu's fixed profiled-launch slot onto scan_kernel
__global__ void prof_pad_kernel() {}

// ======================================================================
__global__ void encode_kernel(const int* __restrict__ sent, const float* __restrict__ emb,
                              const float* __restrict__ Wenc, const float* __restrict__ benc) {
    __shared__ float xsh[8][E];
    __shared__ int tok[8];
    int row0 = blockIdx.x * 8, tid = threadIdx.x;
    if (tid < 8) tok[tid] = sent[row0 + tid];
    __syncthreads();
    for (int i = tid; i < 8 * E; i += 128) {
        int r = i / E, k = i - r * E;
        xsh[r][k] = emb[(long)tok[r] * E + k];
    }
    __syncthreads();
    int c = tid * 4;
    float4 acc[8];
#pragma unroll
    for (int r = 0; r < 8; r++) acc[r] = make_float4(0.f, 0.f, 0.f, 0.f);
    for (int k = 0; k < E; k++) {
        float4 w = *(const float4*)&Wenc[k * D + c];
#pragma unroll
        for (int r = 0; r < 8; r++) {
            float xv = xsh[r][k];
            acc[r].x = __fmaf_rn(xv, w.x, acc[r].x); acc[r].y = __fmaf_rn(xv, w.y, acc[r].y);
            acc[r].z = __fmaf_rn(xv, w.z, acc[r].z); acc[r].w = __fmaf_rn(xv, w.w, acc[r].w);
        }
    }
    float4 bv = *(const float4*)&benc[c];
#pragma unroll
    for (int r = 0; r < 8; r++) {
        acc[r].x += bv.x; acc[r].y += bv.y; acc[r].z += bv.z; acc[r].w += bv.w;
        int gr = row0 + r, b = gr / S, s = gr - b * S;
        *(float4*)&g_states[b][s][c] = acc[r];
    }
}

// ======================================================================
__global__ void initsel_kernel(const float* __restrict__ Ws1, const float* __restrict__ bs1,
                               const float* __restrict__ Ws2, const float* __restrict__ bs2) {
    __shared__ float hs[17][H];
    __shared__ float red[4];
    int b = blockIdx.y, p0 = blockIdx.x * 16, tid = threadIdx.x;
    int nrows = min(17, S - p0);
    for (int i = tid; i < nrows * H; i += 128) {
        int r = i >> 8, k = i & (H - 1);
        hs[r][k] = g_states[b][p0 + r][H + k];
    }
    __syncthreads();
    int npairs = min(16, (S - 1) - p0);
    for (int p = 0; p < npairs; p++) {
        float a[8];
#pragma unroll
        for (int m = 0; m < 8; m++) a[m] = 0.0f;
        const float* wp = Ws1 + tid;
        for (int k = 0; k < 64; k++) {
#pragma unroll
            for (int m = 0; m < 4; m++)
                a[m] = __fmaf_rn(hs[p][m * 64 + k], wp[(m * 64 + k) * SEL], a[m]);
#pragma unroll
            for (int m = 0; m < 4; m++)
                a[4 + m] = __fmaf_rn(hs[p + 1][m * 64 + k], wp[(256 + m * 64 + k) * SEL], a[4 + m]);
        }
        float s = a[0] + a[1] + a[2] + a[3] + a[4] + a[5] + a[6] + a[7] + bs1[tid];
        float y = tanhf(s) * Ws2[tid];
        for (int o = 16; o; o >>= 1) y += __shfl_xor_sync(0xffffffffu, y, o);
        if ((tid & 31) == 0) red[tid >> 5] = y;
        __syncthreads();
        if (tid == 0) g_logits0[b][p0 + p] = red[0] + red[1] + red[2] + red[3] + bs2[0];
        __syncthreads();
    }
}

// ======================================================================
// Scan: 64 CTAs = 8 clusters x 8, 8 batches/cluster.
// CTA r: gate cols h in [32r,32r+32); sel j in [16r,16r+16).
// Fresh-slot state writes; merged h' + phase5 partials travel via DSMEM.
// ======================================================================
__global__ void __cluster_dims__(CL, 1, 1) __launch_bounds__(TPB, 1)
scan_kernel(const float* __restrict__ Wc,  const float* __restrict__ bc,
            const float* __restrict__ Ws1, const float* __restrict__ bs1,
            const float* __restrict__ Ws2, const float* __restrict__ bs2) {
    extern __shared__ char dsm[];
    ull*   xs2  = (ull*)(dsm + O_XS2);
    ull*   xp   = (ull*)(dsm + O_XP);
    ull*   redk = (ull*)(dsm + O_REDK);
    ull*   p5q  = (ull*)(dsm + O_P5Q);
    float* Ws1s = (float*)(dsm + O_WS1S);
    float* bcs  = (float*)(dsm + O_BCS);
    float* lg   = (float*)(dsm + O_LG);
    int*   pmi  = (int*)(dsm + O_PM);
    int*   misc = (int*)(dsm + O_MISC);
    float* clcr = (float*)(dsm + O_CLCR);
    float* xnl  = (float*)(dsm + O_XNL);
    float* xnr  = (float*)(dsm + O_XNR);
    float* hM   = (float*)(dsm + O_HM);
    float* p5a  = (float*)(dsm + O_P5A);   // [rank][16] = rank*16 + b*2 + s
    int* selidx = misc;        int* sLa = misc + 8;   int* sRa = misc + 16;
    int* frs    = misc + 24;   int* fsl = misc + 32;
    float* bs1s = (float*)(misc + 40);
    float* ws2s = (float*)(misc + 56);

    int tid = threadIdx.x;
    int r   = blockIdx.x & (CL - 1);
    int gb0 = (blockIdx.x >> 3) * NB;

    // ---- one-time preloads ----
    for (int i = tid; i < 512 * 16; i += TPB) {
        int k = i >> 4, j16 = i & 15;
        Ws1s[j16 * 524 + k] = Ws1[(size_t)k * SEL + r * 16 + j16];
    }
    if (tid < 160) bcs[tid] = bc[(tid >> 5) * 256 + r * 32 + (tid & 31)];
    if (tid < 16) { bs1s[tid] = bs1[r * 16 + tid]; ws2s[tid] = Ws2[r * 16 + tid]; }
    if (tid < 8)  frs[tid] = 96;
    for (int i = tid; i < NB * (S - 1); i += TPB) {
        int b = i / (S - 1), j = i - b * (S - 1);
        lg[b * 96 + j] = g_logits0[gb0 + b][j];
    }
    for (int i = tid; i < NB * S; i += TPB) {
        int b = i / S, j = i - b * S;
        pmi[b * 96 + j] = j;
    }
    float bs2v = bs2[0];
    __syncthreads();

    // compose geometry
    int wid = tid >> 5, lane = tid & 31;
    int cg  = wid % 5, ckb = wid / 5;
    int cks = lane >> 3, cu4 = lane & 7;
    const float* wpc = Wc + cg * 256 + r * 32 + cu4 * 4;
    int ck0 = ckb * 128 + cks * 2;

    for (int t = 0; t < S - 1; t++) {
        int n = S - t, np = n - 1;

        // ---- argmax (replicated) + free-slot bookkeeping ----
        if (tid < 256) {
            int b = tid >> 5, ln = tid & 31;
            float best = -1e30f; int bi = 0;
            for (int j = ln; j < np; j += 32) {
                float v = lg[b * 96 + j];
                if (v > best) { best = v; bi = j; }
            }
            for (int o = 16; o; o >>= 1) {
                float ov = __shfl_xor_sync(0xffffffffu, best, o);
                int   oi = __shfl_xor_sync(0xffffffffu, bi, o);
                if (ov > best || (ov == best && oi < bi)) { best = ov; bi = oi; }
            }
            if (ln == 0) {
                int sl = pmi[b * 96 + bi], sr = pmi[b * 96 + bi + 1];
                selidx[b] = bi; sLa[b] = sl; sRa[b] = sr;
                fsl[b] = frs[b];
                frs[b] = sr;
            }
        }
        __syncthreads();

        // ---- staging: xs2 + clcr + EARLY neighbor h for phase5 ----
        for (int i = tid; i < NB * D; i += TPB) {
            int b = i >> 9, k = i & (D - 1);
            int slot = (k < H) ? sLa[b] : sRa[b];
            int col  = (k < H) ? (H + k) : k;
            float xv = __ldcg(&g_states[gb0 + b][slot][col]);
            xs2[b * 512 + k] = pack2(xv, xv);
        }
        if (tid < 512) {
            int b = tid >> 6, half = (tid >> 5) & 1, u = tid & 31;
            clcr[(b * 2 + half) * 32 + u] =
                __ldcg(&g_states[gb0 + b][half ? sRa[b] : sLa[b]][r * 32 + u]);
        }
        for (int i = tid; i < NB * H; i += TPB) {       // neighbor h (old states)
            int b = i >> 8, k = i & (H - 1);
            int idx = selidx[b];
            float vL = 0.f, vR = 0.f;
            if (idx >= 1)     vL = __ldcg(&g_states[gb0 + b][pmi[b * 96 + idx - 1]][H + k]);
            if (idx <= n - 3) vR = __ldcg(&g_states[gb0 + b][pmi[b * 96 + idx + 2]][H + k]);
            xnl[b * 256 + k] = vL;
            xnr[b * 256 + k] = vR;
        }
        __syncthreads();

        // ---- compose ----
        {
            ull acc[16];
#pragma unroll
            for (int i = 0; i < 16; i++) acc[i] = 0ull;
#pragma unroll 4
            for (int m = 0; m < 16; m++) {
                int k = ck0 + m * 8;
                ulonglong2 w0 = *(const ulonglong2*)(wpc + (size_t)k * G5);
                ulonglong2 w1 = *(const ulonglong2*)(wpc + (size_t)(k + 1) * G5);
#pragma unroll
                for (int b = 0; b < 8; b++) {
                    ulonglong2 xv = *(const ulonglong2*)&xs2[b * 512 + k];
                    acc[b * 2]     = fma2(w0.x, xv.x, acc[b * 2]);
                    acc[b * 2 + 1] = fma2(w0.y, xv.x, acc[b * 2 + 1]);
                    acc[b * 2]     = fma2(w1.x, xv.y, acc[b * 2]);
                    acc[b * 2 + 1] = fma2(w1.y, xv.y, acc[b * 2 + 1]);
                }
            }
#pragma unroll
            for (int i = 0; i < 16; i++) {
                acc[i] = add2(acc[i], __shfl_xor_sync(0xffffffffu, acc[i], 8));
                acc[i] = add2(acc[i], __shfl_xor_sync(0xffffffffu, acc[i], 16));
            }
            if (cks == 0) {
                ull* dst = &redk[(size_t)(wid * 8 + cu4) * 16];
#pragma unroll
                for (int i = 0; i < 16; i++) dst[i] = acc[i];
            }
        }
        __syncthreads();

        // ---- gates (tid<256, + DSMEM h' bcast) overlapped with shift-read ----
        int spv0 = 0, swp0 = 0, swl0 = 0; float slv0 = 0.f; int sb0 = 0, sj0 = 0;
        int spv1 = 0, swp1 = 0, swl1 = 0; float slv1 = 0.f; int sb1 = 0, sj1 = 0;
        if (tid < 256) {
            int b = tid >> 5, u = tid & 31;
            int u4 = u >> 2, cp = (u >> 1) & 1, half = u & 1;
            float gate[5];
#pragma unroll
            for (int g = 0; g < 5; g++) {
                float s = 0.f;
#pragma unroll
                for (int kb = 0; kb < 4; kb++) {
                    ull v = redk[(size_t)((kb * 5 + g) * 8 + u4) * 16 + b * 2 + cp];
                    s += half ? hi32(v) : lo32(v);
                }
                gate[g] = s + bcs[g * 32 + u];
            }
            int gb = gb0 + b, h = r * 32 + u;
            float cl = clcr[(b * 2 + 0) * 32 + u];
            float cr = clcr[(b * 2 + 1) * 32 + u];
            float cc = sigf(gate[1]) * cl + sigf(gate[2]) * cr + sigf(gate[0]) * tanhf(gate[4]);
            float hp = sigf(gate[3]) * tanhf(cc);
            g_states[gb][fsl[b]][h]     = cc;      // for future steps (via L2)
            g_states[gb][fsl[b]][H + h] = hp;
            // broadcast h' slice to all cluster CTAs' hM (incl. self)
            unsigned la = smem_u32(&hM[b * 256 + h]);
#pragma unroll
            for (int rr = 0; rr < CL; rr++) stc_f32(la, rr, hp);
        } else {
            int ii0 = tid - 256, ii1 = ii0 + 384;
            sb0 = ii0 / 96; sj0 = ii0 - sb0 * 96;
            {
                int idx = selidx[sb0];
                if (sj0 >= idx + 1 && sj0 <= n - 2) { spv0 = pmi[sb0 * 96 + sj0 + 1]; swp0 = 1; }
                if (sj0 >= idx + 1 && sj0 <= n - 3) { slv0 = lg[sb0 * 96 + sj0 + 1]; swl0 = 1; }
            }
            if (ii1 < NB * 96) {
                sb1 = ii1 / 96; sj1 = ii1 - sb1 * 96;
                int idx = selidx[sb1];
                if (sj1 >= idx + 1 && sj1 <= n - 2) { spv1 = pmi[sb1 * 96 + sj1 + 1]; swp1 = 1; }
                if (sj1 >= idx + 1 && sj1 <= n - 3) { slv1 = lg[sb1 * 96 + sj1 + 1]; swl1 = 1; }
            }
        }
        __syncthreads();
        if (tid >= 256) {
            if (swp0) pmi[sb0 * 96 + sj0] = spv0;
            if (swl0) lg[sb0 * 96 + sj0] = slv0;
            if (swp1) pmi[sb1 * 96 + sj1] = spv1;
            if (swl1) lg[sb1 * 96 + sj1] = slv1;
        }
        if (tid < 8) pmi[tid * 96 + selidx[tid]] = fsl[tid];
        cluster_bar();                                   // SYNC1: hM (DSMEM) visible

        // ---- xp pack: pure smem (neighbors early-staged, merged via hM) ----
        for (int i = tid; i < NB * D; i += TPB) {
            int b = i >> 9, k = i & (D - 1);
            int idx = selidx[b];
            bool vA = (idx >= 1);
            bool vB = (idx <= n - 3);
            float xA, xB;
            if (k < H) {
                xA = vA ? xnl[b * 256 + k] : 0.f;
                xB = vB ? hM[b * 256 + k] : 0.f;
            } else {
                xA = vA ? hM[b * 256 + (k - H)] : 0.f;
                xB = vB ? xnr[b * 256 + (k - H)] : 0.f;
            }
            xp[b * 512 + k] = pack2(xA, xB);
        }
        __syncthreads();

        // ---- phase5 partials (smem weights) ----
        if (tid < 512) {
            int j16 = tid & 15, b = (tid >> 4) & 7, kh = tid >> 7;
            const float* wr = Ws1s + j16 * 524 + kh * 128;
            const ull*   xr = xp + b * 512 + kh * 128;
            ull a0 = 0ull, a1 = 0ull;
#pragma unroll 8
            for (int m = 0; m < 32; m++) {
                float4 wv = *(const float4*)(wr + m * 4);
                ulonglong2 x01 = *(const ulonglong2*)(xr + m * 4);
                ulonglong2 x23 = *(const ulonglong2*)(xr + m * 4 + 2);
                a0 = fma2(pack2(wv.x, wv.x), x01.x, a0);
                a1 = fma2(pack2(wv.y, wv.y), x01.y, a1);
                a0 = fma2(pack2(wv.z, wv.z), x23.x, a0);
                a1 = fma2(pack2(wv.w, wv.w), x23.y, a1);
            }
            p5q[tid] = add2(a0, a1);
        }
        __syncthreads();
        if (tid < 128) {
            int j16 = tid & 15, b = tid >> 4;
            ull v = p5q[tid];
            v = add2(v, p5q[128 + tid]); v = add2(v, p5q[256 + tid]); v = add2(v, p5q[384 + tid]);
            float sA = lo32(v) + bs1s[j16], sB = hi32(v) + bs1s[j16];
            float yA = tanhf(sA) * ws2s[j16];
            float yB = tanhf(sB) * ws2s[j16];
#pragma unroll
            for (int o = 1; o < 16; o <<= 1) {
                yA += __shfl_xor_sync(0xffffffffu, yA, o);
                yB += __shfl_xor_sync(0xffffffffu, yB, o);
            }
            if (j16 == 0) {
                unsigned laA = smem_u32(&p5a[r * 16 + b * 2 + 0]);
                unsigned laB = smem_u32(&p5a[r * 16 + b * 2 + 1]);
#pragma unroll
                for (int rr = 0; rr < CL; rr++) { stc_f32(laA, rr, yA); stc_f32(laB, rr, yB); }
            }
        }
        cluster_bar();                                   // SYNC2: p5a visible

        // ---- lg update (ordered rank sum, identical order to R9) ----
        if (tid < 16) {
            int b = tid >> 1, s = tid & 1;
            int q = selidx[b] - 1 + s;
            if (q >= 0 && q <= n - 3) {
                float v = bs2v;
#pragma unroll
                for (int rr = 0; rr < CL; rr++) v += p5a[rr * 16 + b * 2 + s];
                lg[b * 96 + q] = v;
            }
        }
        __syncthreads();
    }

    // ---- root hidden ----
    if (tid < 256) {
        int b = tid >> 5, u = tid & 31;
        g_hroot[gb0 + b][r * 32 + u] = __ldcg(&g_states[gb0 + b][pmi[b * 96]][H + r * 32 + u]);
    }
}

// ======================================================================
__global__ void mlp_l1(const float* __restrict__ Wm1, const float* __restrict__ bm1) {
    __shared__ float hsh[H];
    int b = blockIdx.y, c = blockIdx.x * 256 + threadIdx.x;
    if (threadIdx.x < H) hsh[threadIdx.x] = g_hroot[b][threadIdx.x];
    __syncthreads();
    float acc = bm1[c];
    const float* wp = Wm1 + c;
#pragma unroll 8
    for (int k = 0; k < H; k++) acc = __fmaf_rn(hsh[k], wp[k * MLPD], acc);
    g_x1[b][c] = fmaxf(acc, 0.0f);
}

__global__ void mlp_l2(const float* __restrict__ Wm2, const float* __restrict__ bm2) {
    __shared__ float x1s[MLPD];
    int b = blockIdx.y, c = blockIdx.x * 256 + threadIdx.x;
    for (int i = threadIdx.x; i < MLPD; i += 256) x1s[i] = g_x1[b][i];
    __syncthreads();
    float acc = bm2[c];
    const float* wp = Wm2 + c;
#pragma unroll 8
    for (int k = 0; k < MLPD; k++) acc = __fmaf_rn(x1s[k], wp[k * MLPD], acc);
    g_x2[b][c] = fmaxf(acc, 0.0f);
}

__global__ void mlp_l3(const float* __restrict__ Wout, const float* __restrict__ bout,
                       float* __restrict__ out) {
    __shared__ float red[4][NC];
    int b = blockIdx.x, tid = threadIdx.x;
    float p0 = 0.f, p1 = 0.f, p2 = 0.f;
    for (int k = tid; k < MLPD; k += 128) {
        float xv = g_x2[b][k];
        p0 = __fmaf_rn(xv, Wout[k * NC + 0], p0);
        p1 = __fmaf_rn(xv, Wout[k * NC + 1], p1);
        p2 = __fmaf_rn(xv, Wout[k * NC + 2], p2);
    }
    for (int o = 16; o; o >>= 1) {
        p0 += __shfl_xor_sync(0xffffffffu, p0, o);
        p1 += __shfl_xor_sync(0xffffffffu, p1, o);
        p2 += __shfl_xor_sync(0xffffffffu, p2, o);
    }
    int lane = tid & 31, wrp = tid >> 5;
    if (lane == 0) { red[wrp][0] = p0; red[wrp][1] = p1; red[wrp][2] = p2; }
    __syncthreads();
    if (tid < NC) {
        float s = bout[tid];
        for (int w = 0; w < 4; w++) s += red[w][tid];
        out[b * NC + tid] = s;
    }
}

// ======================================================================
extern "C" void kernel_launch(void* const* d_in, const int* in_sizes, int n_in,
                              void* d_out, int out_size) {
    const int*   sent = (const int*)d_in[0];
    const float* emb  = (const float*)d_in[2];
    const float* Wenc = (const float*)d_in[3];
    const float* benc = (const float*)d_in[4];
    const float* Wc   = (const float*)d_in[5];
    const float* bc   = (const float*)d_in[6];
    const float* Ws1  = (const float*)d_in[7];
    const float* bs1  = (const float*)d_in[8];
    const float* Ws2  = (const float*)d_in[9];
    const float* bs2  = (const float*)d_in[10];
    const float* Wm1  = (const float*)d_in[11];
    const float* bm1  = (const float*)d_in[12];
    const float* Wm2  = (const float*)d_in[13];
    const float* bm2  = (const float*)d_in[14];
    const float* Wout = (const float*)d_in[15];
    const float* bout = (const float*)d_in[16];

    static int smem_set = 0;
    if (!smem_set) {
        cudaFuncSetAttribute(scan_kernel, cudaFuncAttributeMaxDynamicSharedMemorySize, SMEM_SZ);
        smem_set = 1;
    }

    prof_pad_kernel<<<1, 32>>>();   // shifts ncu's profiled slot onto scan_kernel
    encode_kernel<<<768, 128>>>(sent, emb, Wenc, benc);
    initsel_kernel<<<dim3(6, 64), 128>>>(Ws1, bs1, Ws2, bs2);
    scan_kernel<<<64, TPB, SMEM_SZ>>>(Wc, bc, Ws1, bs1, Ws2, bs2);
    mlp_l1<<<dim3(4, B), 256>>>(Wm1, bm1);
    mlp_l2<<<dim3(4, B), 256>>>(Wm2, bm2);
    mlp_l3<<<B, 128>>>(Wout, bout, (float*)d_out);
}